// round 5
// baseline (speedup 1.0000x reference)
#include <cuda_runtime.h>
#include <cstdint>

// SpikeFP32ScaleBy2K — streaming bit-circuit kernel.
//   out = (k == ±0) ? x : x with exponent field := (e_x + kf) & 0xFF
//   kf = s_k ? -|k| : |k|,  |k| = (0x80 | top7(m_k)) >> (7 - ((e_k-127)&7))
// Bits stored big-endian as 0.0/1.0 floats, 32 per row.
//
// R5: MLP=4 with locality preserved. Each block owns 512 consecutive uint4s
// (two adjacent 4KB chunks); thread t handles base+t and base+t+256. All four
// LDG.128 front-batched; 8-lane shuffle groups intact (offset 256 ≡ 0 mod 8).

__global__ __launch_bounds__(256) void spike_scale_kernel(
    const uint4* __restrict__ x,
    const uint4* __restrict__ k,
    uint4* __restrict__ out)
{
    int t0 = blockIdx.x * 512 + threadIdx.x;
    int t1 = t0 + 256;

    const unsigned sh = 28u - 4u * ((unsigned)threadIdx.x & 7u);  // same for both segs

    // Front-batch 4 independent coalesced 16B loads (adjacent 4KB chunks).
    uint4 xu0 = x[t0];
    uint4 ku0 = k[t0];
    uint4 xu1 = x[t1];
    uint4 ku1 = k[t1];

    unsigned xw0 = ((xu0.x ? 8u : 0u) | (xu0.y ? 4u : 0u) |
                    (xu0.z ? 2u : 0u) | (xu0.w ? 1u : 0u)) << sh;
    unsigned kw0 = ((ku0.x ? 8u : 0u) | (ku0.y ? 4u : 0u) |
                    (ku0.z ? 2u : 0u) | (ku0.w ? 1u : 0u)) << sh;
    unsigned xw1 = ((xu1.x ? 8u : 0u) | (xu1.y ? 4u : 0u) |
                    (xu1.z ? 2u : 0u) | (xu1.w ? 1u : 0u)) << sh;
    unsigned kw1 = ((ku1.x ? 8u : 0u) | (ku1.y ? 4u : 0u) |
                    (ku1.z ? 2u : 0u) | (ku1.w ? 1u : 0u)) << sh;

    // OR-butterfly across the 8 contiguous lanes of each row; 4 words in
    // flight per level for SHFL-latency overlap.
    #pragma unroll
    for (int m = 1; m <= 4; m <<= 1) {
        xw0 |= __shfl_xor_sync(0xFFFFFFFFu, xw0, m);
        kw0 |= __shfl_xor_sync(0xFFFFFFFFu, kw0, m);
        xw1 |= __shfl_xor_sync(0xFFFFFFFFu, xw1, m);
        kw1 |= __shfl_xor_sync(0xFFFFFFFFu, kw1, m);
    }

    // Bit circuit, per segment.
    #pragma unroll
    for (int s = 0; s < 2; s++) {
        unsigned xw = s ? xw1 : xw0;
        unsigned kw = s ? kw1 : kw0;

        unsigned e_k   = (kw >> 23) & 0xFFu;
        unsigned s_k   = kw >> 31;
        unsigned kzero = ((kw & 0x7FFFFFFFu) == 0u);

        unsigned sh3  = (e_k - 127u) & 7u;
        unsigned val  = 0x80u | ((kw >> 16) & 0x7Fu);
        unsigned kabs = val >> (7u - sh3);
        unsigned kf   = s_k ? ((0u - kabs) & 0xFFu) : kabs;

        unsigned e_new = (((xw >> 23) & 0xFFu) + kf) & 0xFFu;
        unsigned ow    = kzero ? xw : ((xw & 0x807FFFFFu) | (e_new << 23));

        unsigned b = ow >> sh;
        uint4 o;
        o.x = (b & 8u) ? 0x3F800000u : 0u;
        o.y = (b & 4u) ? 0x3F800000u : 0u;
        o.z = (b & 2u) ? 0x3F800000u : 0u;
        o.w = (b & 1u) ? 0x3F800000u : 0u;
        __stcs(&out[s ? t1 : t0], o);
    }
}

extern "C" void kernel_launch(void* const* d_in, const int* in_sizes, int n_in,
                              void* d_out, int out_size)
{
    const uint4* x = (const uint4*)d_in[0];
    const uint4* k = (const uint4*)d_in[1];
    uint4* o = (uint4*)d_out;

    int n4 = in_sizes[0] / 4;          // 2^24 float4s — divisible by 512
    int blocks = n4 / 512;             // each block owns 512 uint4s
    spike_scale_kernel<<<blocks, 256>>>(x, k, o);
}

// round 6
// speedup vs baseline: 1.0250x; 1.0250x over previous
#include <cuda_runtime.h>
#include <cstdint>

// SpikeFP32ScaleBy2K — streaming bit-circuit kernel (roofline-frozen form).
//   out = (k == ±0) ? x : x with exponent field := (e_x + kf) & 0xFF
//   kf = s_k ? -|k| : |k|,  |k| = (0x80 | top7(m_k)) >> (7 - ((e_k-127)&7))
// Bits stored big-endian as 0.0/1.0 floats, 32 per row.
//
// Layout: 8 lanes per row, one float4 (4 bits) per lane -> fully coalesced
// 16B accesses; row words assembled via 3-level shfl_xor OR-butterfly.
// Measured at 109.4-109.9us kernel / ~6.9TB/s (86-87% of HBM spec) across
// three structural variants — DRAM-bound at the achieved ceiling.
// This version: bit-23 extraction packing (1.0f = 0x3F800000), __stcs
// stores, exact grid (n4 = 2^24 divisible by 256, no tail branch).

__global__ __launch_bounds__(256) void spike_scale_kernel(
    const uint4* __restrict__ x,
    const uint4* __restrict__ k,
    uint4* __restrict__ out)
{
    int t = blockIdx.x * blockDim.x + threadIdx.x;

    const unsigned sh = 28u - 4u * ((unsigned)t & 7u);   // nibble pos (BE order)

    uint4 xu = x[t];
    uint4 ku = k[t];

    // Pack via bit 23: 1.0f has it set, 0.0f doesn't. SHF+LOP3-fusable.
    unsigned xw = ( ((xu.x >> 20) & 8u) | ((xu.y >> 21) & 4u) |
                    ((xu.z >> 22) & 2u) | ((xu.w >> 23) & 1u) ) << sh;
    unsigned kw = ( ((ku.x >> 20) & 8u) | ((ku.y >> 21) & 4u) |
                    ((ku.z >> 22) & 2u) | ((ku.w >> 23) & 1u) ) << sh;

    // OR-butterfly across the 8 contiguous lanes of this row.
    #pragma unroll
    for (int m = 1; m <= 4; m <<= 1) {
        xw |= __shfl_xor_sync(0xFFFFFFFFu, xw, m);
        kw |= __shfl_xor_sync(0xFFFFFFFFu, kw, m);
    }
    // xw/kw now hold full words: sign@31, exp@30..23, mant@22..0.

    unsigned e_k   = (kw >> 23) & 0xFFu;
    unsigned s_k   = kw >> 31;
    unsigned kzero = ((kw & 0x7FFFFFFFu) == 0u);

    unsigned sh3  = (e_k - 127u) & 7u;
    unsigned val  = 0x80u | ((kw >> 16) & 0x7Fu);
    unsigned kabs = val >> (7u - sh3);
    unsigned kf   = s_k ? ((0u - kabs) & 0xFFu) : kabs;

    unsigned e_new = (((xw >> 23) & 0xFFu) + kf) & 0xFFu;
    unsigned ow    = kzero ? xw : ((xw & 0x807FFFFFu) | (e_new << 23));

    // Unpack this lane's 4 output bits; store non-temporal (never re-read).
    unsigned b = ow >> sh;
    uint4 o;
    o.x = (b & 8u) ? 0x3F800000u : 0u;
    o.y = (b & 4u) ? 0x3F800000u : 0u;
    o.z = (b & 2u) ? 0x3F800000u : 0u;
    o.w = (b & 1u) ? 0x3F800000u : 0u;
    __stcs(&out[t], o);
}

extern "C" void kernel_launch(void* const* d_in, const int* in_sizes, int n_in,
                              void* d_out, int out_size)
{
    const uint4* x = (const uint4*)d_in[0];
    const uint4* k = (const uint4*)d_in[1];
    uint4* o = (uint4*)d_out;

    int n4 = in_sizes[0] / 4;          // 2^24 float4s — divisible by 256
    int threads = 256;
    int blocks  = n4 / threads;        // exact; no tail
    spike_scale_kernel<<<blocks, threads>>>(x, k, o);
}